// round 2
// baseline (speedup 1.0000x reference)
#include <cuda_runtime.h>

#define BATCH 32
#define CCH   256
#define HW    1024
#define TILE  128
#define KT    16
#define INV_T 14.285714285714286f   // 1 / 0.07

// ---------------- scratch (static device globals: no allocation) ----------------
__device__ float    g_At[(size_t)BATCH * CCH * HW];     // 32 MB : A transposed (w,h)->j
__device__ float    g_M [(size_t)BATCH * HW * HW];      // 128 MB: G[b][j][i] = M[b][i][j]/T
__device__ unsigned g_maxIk[BATCH * HW];                // ordered-uint keys of maxI[i]
__device__ unsigned g_maxJk[BATCH * HW];                // ordered-uint keys of maxJ[j]
__device__ float    g_sumI[BATCH * HW];
__device__ float    g_sumJ[BATCH * HW];

// ---------------- helpers ----------------
__device__ __forceinline__ unsigned fkey(float f) {
    unsigned u = __float_as_uint(f);
    return u ^ ((unsigned)(((int)u) >> 31) | 0x80000000u);  // monotone float->uint
}
__device__ __forceinline__ float kdec(unsigned k) {
    unsigned u = (k & 0x80000000u) ? (k ^ 0x80000000u) : ~k;
    return __uint_as_float(u);
}

// packed 2xFP32 FMA (Blackwell f32x2 pipe; 2 FMA per lane-instr)
__device__ __forceinline__ void fma2(unsigned long long& d, unsigned long long a,
                                     unsigned long long b) {
    asm("fma.rn.f32x2 %0, %1, %2, %0;" : "+l"(d) : "l"(a), "l"(b));
}
__device__ __forceinline__ unsigned long long pack2(float x, float y) {
    unsigned long long r;
    asm("mov.b64 %0, {%1, %2};" : "=l"(r) : "f"(x), "f"(y));
    return r;
}
__device__ __forceinline__ float2 unpack2(unsigned long long v) {
    float2 f;
    asm("mov.b64 {%0, %1}, %2;" : "=f"(f.x), "=f"(f.y) : "l"(v));
    return f;
}

// ---------------- K0a: reset stats (must run every graph replay) ----------------
__global__ void k_init() {
    int idx = blockIdx.x * blockDim.x + threadIdx.x;
    if (idx < BATCH * HW) {
        g_maxIk[idx] = 0u;   // below fkey of any real value
        g_maxJk[idx] = 0u;
        g_sumI[idx]  = 0.f;
        g_sumJ[idx]  = 0.f;
    }
}

// ---------------- K0b: A_flat[b][c][j] = A[b][c][j%32][j/32] ----------------
__global__ __launch_bounds__(256) void k_transpose(const float* __restrict__ A) {
    __shared__ float s[32][33];
    const size_t plane = blockIdx.x;  // b*C + c
    const float* Ap = A + plane * 1024;
    float*       Op = g_At + plane * 1024;
    const int t = threadIdx.x;
#pragma unroll
    for (int l = 0; l < 4; l++) {
        int idx = t + l * 256;
        s[idx >> 5][idx & 31] = Ap[idx];
    }
    __syncthreads();
#pragma unroll
    for (int l = 0; l < 4; l++) {
        int idx = t + l * 256;
        Op[idx] = s[idx & 31][idx >> 5];   // At[j] = A[h=j%32][w=j/32]
    }
}

// ---------------- K1: G[b][j][i] = (1/T) * sum_c At[c][j]*B[c][i]  + maxes ------
__global__ __launch_bounds__(256, 2) void k_gemm(const float* __restrict__ Bf) {
    __shared__ float sA[KT][TILE];
    __shared__ float sB[KT][TILE];
    __shared__ float red[16][TILE];

    const int b  = blockIdx.z;
    const int i0 = blockIdx.x * TILE;
    const int j0 = blockIdx.y * TILE;
    const float* __restrict__ Bp = Bf   + (size_t)b * CCH * HW;  // [c][i]
    const float* __restrict__ Ap = g_At + (size_t)b * CCH * HW;  // [c][j]

    const int t  = threadIdx.x;
    const int tx = t & 15, ty = t >> 4;
    const int ldk = t >> 5;          // 0..7
    const int ldc = (t & 31) << 2;   // 0,4,...,124

    unsigned long long acc[8][4];
#pragma unroll
    for (int j = 0; j < 8; j++)
#pragma unroll
        for (int q = 0; q < 4; q++) acc[j][q] = 0ULL;

    // prefetch first K-slice
    float4 pa0 = *(const float4*)(Ap + (size_t)ldk * HW + j0 + ldc);
    float4 pa1 = *(const float4*)(Ap + (size_t)(ldk + 8) * HW + j0 + ldc);
    float4 pb0 = *(const float4*)(Bp + (size_t)ldk * HW + i0 + ldc);
    float4 pb1 = *(const float4*)(Bp + (size_t)(ldk + 8) * HW + i0 + ldc);

    for (int k0 = 0; k0 < CCH; k0 += KT) {
        __syncthreads();
        *(float4*)&sA[ldk][ldc]     = pa0;
        *(float4*)&sA[ldk + 8][ldc] = pa1;
        *(float4*)&sB[ldk][ldc]     = pb0;
        *(float4*)&sB[ldk + 8][ldc] = pb1;
        __syncthreads();
        if (k0 + KT < CCH) {
            const int kn = k0 + KT;
            pa0 = *(const float4*)(Ap + (size_t)(kn + ldk) * HW + j0 + ldc);
            pa1 = *(const float4*)(Ap + (size_t)(kn + ldk + 8) * HW + j0 + ldc);
            pb0 = *(const float4*)(Bp + (size_t)(kn + ldk) * HW + i0 + ldc);
            pb1 = *(const float4*)(Bp + (size_t)(kn + ldk + 8) * HW + i0 + ldc);
        }
#pragma unroll
        for (int kk = 0; kk < KT; kk++) {
            // B pairs loaded directly as 64-bit packed operands
            ulonglong2 u0 = *(const ulonglong2*)&sB[kk][tx << 2];
            ulonglong2 u1 = *(const ulonglong2*)&sB[kk][64 + (tx << 2)];
            unsigned long long bp[4] = {u0.x, u0.y, u1.x, u1.y};
            float4 aA = *(const float4*)&sA[kk][ty << 2];
            float4 aB = *(const float4*)&sA[kk][64 + (ty << 2)];
            float aj[8] = {aA.x, aA.y, aA.z, aA.w, aB.x, aB.y, aB.z, aB.w};
#pragma unroll
            for (int j = 0; j < 8; j++) {
                unsigned long long a2 = pack2(aj[j], aj[j]);
#pragma unroll
                for (int q = 0; q < 4; q++) fma2(acc[j][q], a2, bp[q]);
            }
        }
    }

    // unpack accumulators, apply 1/TEMPERATURE
    float av[8][8];
#pragma unroll
    for (int j = 0; j < 8; j++)
#pragma unroll
        for (int q = 0; q < 4; q++) {
            float2 f = unpack2(acc[j][q]);
            av[j][2 * q]     = f.x * INV_T;
            av[j][2 * q + 1] = f.y * INV_T;
        }

    // store G (coalesced float4 per 16-lane group)
#pragma unroll
    for (int j = 0; j < 8; j++) {
        const int jl = (j < 4) ? (ty * 4 + j) : (64 + ty * 4 + (j - 4));
        float* row = g_M + ((size_t)b * HW + j0 + jl) * HW + i0;
        *(float4*)(row + (tx << 2))      = make_float4(av[j][0], av[j][1], av[j][2], av[j][3]);
        *(float4*)(row + 64 + (tx << 2)) = make_float4(av[j][4], av[j][5], av[j][6], av[j][7]);
    }

    // per-thread maxes over micro-tile
    float mi[8], mj[8];
#pragma unroll
    for (int ii = 0; ii < 8; ii++) {
        float m = av[0][ii];
#pragma unroll
        for (int j = 1; j < 8; j++) m = fmaxf(m, av[j][ii]);
        mi[ii] = m;
    }
#pragma unroll
    for (int j = 0; j < 8; j++) {
        float m = av[j][0];
#pragma unroll
        for (int ii = 1; ii < 8; ii++) m = fmaxf(m, av[j][ii]);
        mj[j] = m;
    }

    // reduce maxI over j within tile, then global atomicMax
    __syncthreads();
#pragma unroll
    for (int idx = 0; idx < 8; idx++) {
        const int il = (idx < 4) ? (tx * 4 + idx) : (64 + tx * 4 + (idx - 4));
        red[ty][il] = mi[idx];
    }
    __syncthreads();
    if (t < TILE) {
        float m = red[0][t];
#pragma unroll
        for (int r = 1; r < 16; r++) m = fmaxf(m, red[r][t]);
        atomicMax(&g_maxIk[b * HW + i0 + t], fkey(m));
    }
    __syncthreads();
#pragma unroll
    for (int j = 0; j < 8; j++) {
        const int jl = (j < 4) ? (ty * 4 + j) : (64 + ty * 4 + (j - 4));
        red[tx][jl] = mj[j];
    }
    __syncthreads();
    if (t < TILE) {
        float m = red[0][t];
#pragma unroll
        for (int r = 1; r < 16; r++) m = fmaxf(m, red[r][t]);
        atomicMax(&g_maxJk[b * HW + j0 + t], fkey(m));
    }
}

// ---------------- K2: fused exp-sum stats (one pass over G) ----------------
__global__ __launch_bounds__(256) void k_stats() {
    __shared__ float mI[TILE], mJ[TILE], sJ[TILE], sIa[256];
    const int b = blockIdx.z, i0 = blockIdx.x * TILE, j0 = blockIdx.y * TILE;
    const int t = threadIdx.x;
    if (t < TILE) {
        mI[t] = kdec(g_maxIk[b * HW + i0 + t]);
        mJ[t] = kdec(g_maxJk[b * HW + j0 + t]);
        sJ[t] = 0.f;
    }
    __syncthreads();
    const int ii = t & 127, half = t >> 7;
    const float* Gp = g_M + ((size_t)b * HW + j0) * HW + i0;
    const float mIi = mI[ii];
    float accI = 0.f;
#pragma unroll 4
    for (int jj = half; jj < TILE; jj += 2) {
        float g = Gp[(size_t)jj * HW + ii];
        accI += __expf(g - mIi);
        float e2 = __expf(g - mJ[jj]);
#pragma unroll
        for (int off = 16; off > 0; off >>= 1) e2 += __shfl_xor_sync(0xffffffffu, e2, off);
        if ((t & 31) == 0) atomicAdd(&sJ[jj], e2);
    }
    sIa[t] = accI;
    __syncthreads();
    if (t < TILE) {
        atomicAdd(&g_sumI[b * HW + i0 + t], sIa[t] + sIa[t + TILE]);
        atomicAdd(&g_sumJ[b * HW + j0 + t], sJ[t]);
    }
}

// ---------------- K3: out[b][j][i] = exp(2G - mI - mJ)/(sI*sJ) ----------------
__global__ __launch_bounds__(256) void k_final(float* __restrict__ out) {
    __shared__ float mI[TILE], mJ[TILE], rI[TILE], rJ[TILE];
    const int b = blockIdx.z, i0 = blockIdx.x * TILE, j0 = blockIdx.y * TILE;
    const int t = threadIdx.x;
    if (t < TILE) {
        mI[t] = kdec(g_maxIk[b * HW + i0 + t]);
        mJ[t] = kdec(g_maxJk[b * HW + j0 + t]);
        rI[t] = 1.0f / g_sumI[b * HW + i0 + t];
        rJ[t] = 1.0f / g_sumJ[b * HW + j0 + t];
    }
    __syncthreads();
    const float* Gp = g_M + ((size_t)b * HW + j0) * HW + i0;
    float*       Op = out + ((size_t)b * HW + j0) * HW + i0;
#pragma unroll 4
    for (int idx = t; idx < TILE * TILE; idx += 256) {
        const int jj = idx >> 7, ii = idx & 127;
        float g = Gp[(size_t)jj * HW + ii];
        Op[(size_t)jj * HW + ii] =
            __expf(2.f * g - mI[ii] - mJ[jj]) * rI[ii] * rJ[jj];
    }
}

// ---------------- launch ----------------
extern "C" void kernel_launch(void* const* d_in, const int* in_sizes, int n_in,
                              void* d_out, int out_size) {
    const float* A  = (const float*)d_in[0];
    const float* Bf = (const float*)d_in[1];
    float* out = (float*)d_out;

    k_init<<<(BATCH * HW + 255) / 256, 256>>>();
    k_transpose<<<BATCH * CCH, 256>>>(A);
    dim3 grid(HW / TILE, HW / TILE, BATCH);
    k_gemm<<<grid, 256>>>(Bf);
    k_stats<<<grid, 256>>>();
    k_final<<<grid, 256>>>(out);
}